// round 1
// baseline (speedup 1.0000x reference)
#include <cuda_runtime.h>
#include <math.h>
#include <math_constants.h>

// Sliding-window causal GQA attention, fp32.
// B=2, S=2048, 8 kv heads x 4 q-heads, D=64, WINDOW=128.
// One CTA per (batch, kv_head, 256-query block): 128 CTAs, 512 threads.
// K/V window staged in smem (K chunk-XOR-swizzled), warp = one query,
// all 4 GQA heads computed together.

namespace {

constexpr int SEQ   = 2048;
constexpr int HK    = 8;     // kv heads
constexpr int QM    = 4;     // q heads per kv head
constexpr int DIM   = 64;
constexpr int WIN   = 128;
constexpr int QBLK  = 256;
constexpr int NWARP = 16;
constexpr int NTHR  = NWARP * 32;
constexpr int ROWS  = QBLK + WIN - 1;   // 383 key rows per tile

constexpr int KS_F = ROWS * DIM;        // 24512 floats
constexpr int VS_F = ROWS * DIM;        // 24512 floats
constexpr int WB_F = 512;               // per-warp scratch (Q stage / probs)
constexpr size_t SMEM_BYTES = (size_t)(KS_F + VS_F + NWARP * WB_F) * sizeof(float); // 228,864 B

__global__ void __launch_bounds__(NTHR, 1)
swa_kernel(const float* __restrict__ Qg,
           const float* __restrict__ Kg,
           const float* __restrict__ Vg,
           float* __restrict__ Og)
{
    extern __shared__ float sm[];
    float* Ks = sm;
    float* Vs = sm + KS_F;

    const int qb  = blockIdx.x;
    const int kvh = blockIdx.y;
    const int b   = blockIdx.z;
    const int q0  = qb * QBLK;
    const int base = q0 - (WIN - 1);    // key index of tile row 0 (may be <0)

    const int tid = threadIdx.x;

    // ---- stage K/V window: 16 threads per row (16 x float4) ----
    {
        const int d4 = tid & 15;
        for (int r = tid >> 4; r < ROWS; r += NTHR / 16) {
            const int key = base + r;
            if (key >= 0) {  // key < SEQ always holds for this grid
                const size_t off = ((size_t)(b * SEQ + key) * HK + kvh) * DIM + d4 * 4;
                const float4 kv = *reinterpret_cast<const float4*>(Kg + off);
                const float4 vv = *reinterpret_cast<const float4*>(Vg + off);
                // K: XOR-swizzle 16B chunks so row-indexed per-lane reads are conflict-free
                reinterpret_cast<float4*>(Ks + r * DIM)[d4 ^ (r & 7)] = kv;
                // V: read pattern is same-row broadcast -> no swizzle needed
                reinterpret_cast<float4*>(Vs + r * DIM)[d4] = vv;
            }
        }
    }
    __syncthreads();

    const int warp = tid >> 5;
    const int lane = tid & 31;
    float* wb = sm + KS_F + VS_F + warp * WB_F;

    constexpr float SCALE = 0.125f;   // 1/sqrt(64)
    const int m0  = lane >> 4;        // PV task: head parity (0/1)
    const int vd4 = lane & 15;        // PV task: float4 column

    for (int it = 0; it < QBLK / NWARP; ++it) {
        const int q = q0 + warp * (QBLK / NWARP) + it;
        int kmin = q - (WIN - 1); if (kmin < 0) kmin = 0;
        const int L = q - kmin + 1;        // valid window length (1..128)
        const int rbase = kmin - base;     // tile row of first valid key

        // ---- stage Q (4 heads x 64 = 256 floats) into wb[0..255] ----
        const float4* qsrc = reinterpret_cast<const float4*>(
            Qg + ((size_t)(b * SEQ + q) * HK * QM + kvh * QM) * DIM);
        reinterpret_cast<float4*>(wb)[lane]      = qsrc[lane];
        reinterpret_cast<float4*>(wb)[lane + 32] = qsrc[lane + 32];
        __syncwarp();

        // ---- QK^T: lane owns keys j = lane + 32*slot, computes all 4 heads ----
        float acc[4][4];
#pragma unroll
        for (int s = 0; s < 4; ++s)
#pragma unroll
            for (int m = 0; m < 4; ++m) acc[s][m] = 0.f;

        int rr[4];
#pragma unroll
        for (int s = 0; s < 4; ++s) rr[s] = rbase + lane + 32 * s;

#pragma unroll 4
        for (int d4 = 0; d4 < 16; ++d4) {
            float4 q4[4];
#pragma unroll
            for (int m = 0; m < 4; ++m)
                q4[m] = reinterpret_cast<const float4*>(wb)[m * 16 + d4];  // broadcast
#pragma unroll
            for (int s = 0; s < 4; ++s) {
                const float4 k4 =
                    reinterpret_cast<const float4*>(Ks + rr[s] * DIM)[d4 ^ (rr[s] & 7)];
#pragma unroll
                for (int m = 0; m < 4; ++m) {
                    acc[s][m] = fmaf(q4[m].x, k4.x,
                                fmaf(q4[m].y, k4.y,
                                fmaf(q4[m].z, k4.z,
                                fmaf(q4[m].w, k4.w, acc[s][m]))));
                }
            }
        }

        // ---- mask + softmax (per head m over 128 slots) ----
        float mx[4], sum[4];
#pragma unroll
        for (int m = 0; m < 4; ++m) mx[m] = -CUDART_INF_F;
#pragma unroll
        for (int s = 0; s < 4; ++s) {
            const bool ok = (lane + 32 * s) < L;
#pragma unroll
            for (int m = 0; m < 4; ++m) {
                acc[s][m] = ok ? acc[s][m] * SCALE : -CUDART_INF_F;
                mx[m] = fmaxf(mx[m], acc[s][m]);
            }
        }
#pragma unroll
        for (int off = 16; off > 0; off >>= 1)
#pragma unroll
            for (int m = 0; m < 4; ++m)
                mx[m] = fmaxf(mx[m], __shfl_xor_sync(0xffffffffu, mx[m], off));

#pragma unroll
        for (int m = 0; m < 4; ++m) sum[m] = 0.f;
        __syncwarp();   // Q staging fully consumed before wb is reused for probs
#pragma unroll
        for (int s = 0; s < 4; ++s)
#pragma unroll
            for (int m = 0; m < 4; ++m) {
                const float e = __expf(acc[s][m] - mx[m]);  // exp(-inf)=0 for masked
                sum[m] += e;
                wb[m * WIN + lane + 32 * s] = e;
            }
#pragma unroll
        for (int off = 16; off > 0; off >>= 1)
#pragma unroll
            for (int m = 0; m < 4; ++m)
                sum[m] += __shfl_xor_sync(0xffffffffu, sum[m], off);
        __syncwarp();

        // ---- PV: lane owns (head m0, d4) and (head m0+2, d4) float4 accumulators ----
        float4 a0 = make_float4(0.f, 0.f, 0.f, 0.f);
        float4 a1 = make_float4(0.f, 0.f, 0.f, 0.f);
        const float* p0 = wb + m0 * WIN;
        const float* p1 = wb + (m0 + 2) * WIN;
        const float4* vrow = reinterpret_cast<const float4*>(Vs + rbase * DIM) + vd4;

#pragma unroll 4
        for (int j = 0; j < L; ++j) {
            const float4 v4 = vrow[(size_t)j * 16];
            const float pa = p0[j];
            const float pb = p1[j];
            a0.x = fmaf(pa, v4.x, a0.x); a0.y = fmaf(pa, v4.y, a0.y);
            a0.z = fmaf(pa, v4.z, a0.z); a0.w = fmaf(pa, v4.w, a0.w);
            a1.x = fmaf(pb, v4.x, a1.x); a1.y = fmaf(pb, v4.y, a1.y);
            a1.z = fmaf(pb, v4.z, a1.z); a1.w = fmaf(pb, v4.w, a1.w);
        }

        const float inv0 = 1.f / ((m0 == 0) ? sum[0] : sum[1]);
        const float inv1 = 1.f / ((m0 == 0) ? sum[2] : sum[3]);
        const float4 o0 = make_float4(a0.x * inv0, a0.y * inv0, a0.z * inv0, a0.w * inv0);
        const float4 o1 = make_float4(a1.x * inv1, a1.y * inv1, a1.z * inv1, a1.w * inv1);

        float4* ob = reinterpret_cast<float4*>(
            Og + (((size_t)(b * SEQ + q) * HK + kvh) * QM) * DIM);
        ob[m0 * 16 + vd4]       = o0;
        ob[(m0 + 2) * 16 + vd4] = o1;

        __syncwarp();   // wb reused for next query's Q staging
    }
}

} // namespace

extern "C" void kernel_launch(void* const* d_in, const int* in_sizes, int n_in,
                              void* d_out, int out_size)
{
    (void)in_sizes; (void)n_in; (void)out_size;
    const float* Q = (const float*)d_in[0];
    const float* K = (const float*)d_in[1];
    const float* V = (const float*)d_in[2];
    // d_in[3] = sinks — unused by the reference math, faithfully ignored.
    float* O = (float*)d_out;

    cudaFuncSetAttribute(swa_kernel, cudaFuncAttributeMaxDynamicSharedMemorySize,
                         (int)SMEM_BYTES);

    dim3 grid(SEQ / QBLK, HK, 2 /*BATCH*/);
    swa_kernel<<<grid, NTHR, SMEM_BYTES>>>(Q, K, V, O);
}